// round 7
// baseline (speedup 1.0000x reference)
#include <cuda_runtime.h>

#define NG   1024
#define IMGW 192
#define IMGH 192
#define NPIX (IMGW*IMGH)
#define TS   8          // tile size
#define NSEG 4          // depth segments per pixel

// Unsorted scratch (written then re-read within the fused block via L1/L2):
__device__ float4 g_p0[NG], g_p1[NG], g_p2[NG];
// Depth-sorted records for render; s1.w = sorted index (for color lookup).
__device__ float4 g_s0[NG], g_s1[NG], g_s2[NG];

// ONE block, 1024 threads: thread t preprocesses gaussian t (key in register),
// then hybrid bitonic sort (shfl j<32, shared j>=32), then gather sorted SoA.
__global__ void __launch_bounds__(NG) fused_pre_sort_kernel(
                                  const float* __restrict__ means,
                                  const float* __restrict__ scales,
                                  const float* __restrict__ rots,
                                  const float* __restrict__ opac,
                                  const float* __restrict__ shs,
                                  const float* __restrict__ view,
                                  const float* __restrict__ proj,
                                  const float* __restrict__ campos,
                                  float* __restrict__ out)
{
    __shared__ unsigned long long sk[NG];
    int i = threadIdx.x;
    float mx = means[3*i], my = means[3*i+1], mz = means[3*i+2];

    // ---- issue all 12 SH float4 loads up front (MLP=12, register resident) ----
    float4 t[12];
    const float4* sh4 = reinterpret_cast<const float4*>(shs + i*48);
    #pragma unroll
    for (int w = 0; w < 12; w++) t[w] = __ldg(sh4 + w);

    // ---- SH degree-3 basis ----
    float dxc = mx - campos[0], dyc = my - campos[1], dzc = mz - campos[2];
    float inv = rsqrtf(dxc*dxc + dyc*dyc + dzc*dzc);
    float x = dxc*inv, y = dyc*inv, z = dzc*inv;
    float xx = x*x, yy = y*y, zz = z*z, xy = x*y, yz = y*z, xz = x*z;
    float bas[16];
    bas[0]  = 0.28209479177387814f;
    bas[1]  = -0.4886025119029199f * y;
    bas[2]  =  0.4886025119029199f * z;
    bas[3]  = -0.4886025119029199f * x;
    bas[4]  =  1.0925484305920792f * xy;
    bas[5]  = -1.0925484305920792f * yz;
    bas[6]  =  0.31539156525252005f * (2.0f*zz - xx - yy);
    bas[7]  = -1.0925484305920792f * xz;
    bas[8]  =  0.5462742152960396f * (xx - yy);
    bas[9]  = -0.5900435899266435f * y * (3.0f*xx - yy);
    bas[10] =  2.890611442640554f  * xy * z;
    bas[11] = -0.4570457994644658f * y * (4.0f*zz - xx - yy);
    bas[12] =  0.3731763325901154f * z * (2.0f*zz - 3.0f*xx - 3.0f*yy);
    bas[13] = -0.4570457994644658f * x * (4.0f*zz - xx - yy);
    bas[14] =  1.445305721320277f  * z * (xx - yy);
    bas[15] = -0.5900435899266435f * x * (xx - yy - 3.0f*zz);

    float col[3] = {0.5f, 0.5f, 0.5f};
    #pragma unroll
    for (int w = 0; w < 12; w++) {
        float v[4] = {t[w].x, t[w].y, t[w].z, t[w].w};
        #pragma unroll
        for (int j = 0; j < 4; j++) {
            const int flat = 4*w + j;
            col[flat % 3] += bas[flat / 3] * v[j];
        }
    }
    col[0] = fmaxf(col[0], 0.0f);
    col[1] = fmaxf(col[1], 0.0f);
    col[2] = fmaxf(col[2], 0.0f);

    // ---- cov3d = (R*S)(R*S)^T ----
    float4 q = __ldg(reinterpret_cast<const float4*>(rots) + i);
    float qr = q.x, qx = q.y, qy = q.z, qz = q.w;
    float sx = scales[3*i], sy = scales[3*i+1], sz = scales[3*i+2];
    float R00 = 1.0f-2.0f*(qy*qy+qz*qz), R01 = 2.0f*(qx*qy-qr*qz), R02 = 2.0f*(qx*qz+qr*qy);
    float R10 = 2.0f*(qx*qy+qr*qz), R11 = 1.0f-2.0f*(qx*qx+qz*qz), R12 = 2.0f*(qy*qz-qr*qx);
    float R20 = 2.0f*(qx*qz-qr*qy), R21 = 2.0f*(qy*qz+qr*qx), R22 = 1.0f-2.0f*(qx*qx+qy*qy);
    float M00=R00*sx, M01=R01*sy, M02=R02*sz;
    float M10=R10*sx, M11=R11*sy, M12=R12*sz;
    float M20=R20*sx, M21=R21*sy, M22=R22*sz;
    float c00 = M00*M00+M01*M01+M02*M02;
    float c01 = M00*M10+M01*M11+M02*M12;
    float c02 = M00*M20+M01*M21+M02*M22;
    float c11 = M10*M10+M11*M11+M12*M12;
    float c12 = M10*M20+M11*M21+M12*M22;
    float c22 = M20*M20+M21*M21+M22*M22;

    // ---- view / projection ----
    float pvx = view[0]*mx + view[1]*my + view[2]*mz + view[3];
    float pvy = view[4]*mx + view[5]*my + view[6]*mz + view[7];
    float pvz = view[8]*mx + view[9]*my + view[10]*mz + view[11];
    float phx = proj[0]*mx + proj[1]*my + proj[2]*mz + proj[3];
    float phy = proj[4]*mx + proj[5]*my + proj[6]*mz + proj[7];
    float phw = proj[12]*mx + proj[13]*my + proj[14]*mz + proj[15];
    float invw = 1.0f / (phw + 1e-7f);
    float gx = ((phx*invw + 1.0f) * (float)IMGW - 1.0f) * 0.5f;
    float gy = ((phy*invw + 1.0f) * (float)IMGH - 1.0f) * 0.5f;
    float depth = pvz;
    bool in_front = depth > 0.2f;
    float tz = in_front ? depth : 1.0f;
    const float lim = 1.3f * 0.5f;
    float txv = fminf(fmaxf(pvx/tz, -lim), lim) * tz;
    float tyv = fminf(fmaxf(pvy/tz, -lim), lim) * tz;
    const float fx = (float)IMGW / (2.0f*0.5f);
    const float fy = (float)IMGH / (2.0f*0.5f);
    float J00 = fx/tz, J02 = -fx*txv/(tz*tz);
    float J11 = fy/tz, J12 = -fy*tyv/(tz*tz);
    float T00 = J00*view[0] + J02*view[8];
    float T01 = J00*view[1] + J02*view[9];
    float T02 = J00*view[2] + J02*view[10];
    float T10 = J11*view[4] + J12*view[8];
    float T11 = J11*view[5] + J12*view[9];
    float T12 = J11*view[6] + J12*view[10];
    float u0 = c00*T00 + c01*T01 + c02*T02;
    float u1 = c01*T00 + c11*T01 + c12*T02;
    float u2 = c02*T00 + c12*T01 + c22*T02;
    float v0 = c00*T10 + c01*T11 + c02*T12;
    float v1 = c01*T10 + c11*T11 + c12*T12;
    float v2 = c02*T10 + c12*T11 + c22*T12;
    float a  = T00*u0 + T01*u1 + T02*u2 + 0.3f;
    float b  = T10*u0 + T11*u1 + T12*u2;
    float cc = T10*v0 + T11*v1 + T12*v2 + 0.3f;
    float det = a*cc - b*b;
    bool pos_det = det > 0.0f;
    float inv_det = pos_det ? 1.0f/det : 0.0f;
    float conA = cc*inv_det, conB = -b*inv_det, conC = a*inv_det;
    float mid = 0.5f*(a + cc);
    float lam = mid + sqrtf(fmaxf(mid*mid - det, 0.1f));
    bool visible = in_front && pos_det;
    float radius = visible ? ceilf(3.0f * sqrtf(lam)) : 0.0f;
    float op = opac[i];

    g_p0[i] = make_float4(gx, gy, radius, visible ? op : 0.0f);
    g_p1[i] = make_float4(conA, conB, conC, depth);
    g_p2[i] = make_float4(col[0], col[1], col[2], 0.0f);

    // aux outputs: radii, visibility_filter, means2D
    out[3*NPIX + i]            = radius;
    out[3*NPIX + NG + i]       = (radius > 0.0f) ? 1.0f : 0.0f;
    out[3*NPIX + 2*NG + 2*i]   = gx;
    out[3*NPIX + 2*NG + 2*i+1] = gy;

    // ---- hybrid bitonic sort: key already in register ----
    unsigned int dbits = visible ? __float_as_uint(depth) : 0x7f800000u; // +inf
    unsigned long long v = ((unsigned long long)dbits << 32) | (unsigned int)i;
    __syncthreads();   // all g_p writes done before gather below
    #pragma unroll 1
    for (int k = 2; k <= NG; k <<= 1) {
        bool up = ((i & k) == 0);
        #pragma unroll 1
        for (int j = k >> 1; j > 0; j >>= 1) {
            unsigned long long p;
            if (j >= 32) {
                __syncthreads();
                sk[i] = v;
                __syncthreads();
                p = sk[i ^ j];
            } else {
                p = __shfl_xor_sync(0xffffffffu, v, j);
            }
            bool lower = (i & j) == 0;
            bool takeMin = (lower == up);
            if (takeMin ? (p < v) : (p > v)) v = p;
        }
    }
    // ---- gather in depth order ----
    int idx = (int)(v & 0x3ffULL);
    float4 f1 = g_p1[idx];
    g_s0[i] = g_p0[idx];
    g_s1[i] = make_float4(f1.x, f1.y, f1.z, (float)i);  // w = sorted index
    g_s2[i] = g_p2[idx];
}

// One block per 8x8 tile, 256 threads = 64 pixels x 4 depth segments.
// Phase 1: order-preserving compaction from the depth-sorted arrays
//          (=> tile list is already depth-sorted, no per-tile sort).
// Phase 2: each of 4 threads per pixel blends one contiguous depth segment;
//          partials composed associatively: (C,T)o(C',T') = (C + T C', T T').
__global__ void __launch_bounds__(256) render_kernel(const float* __restrict__ bg,
                                                     float* __restrict__ out)
{
    __shared__ float4 s_f0[NG];
    __shared__ float4 s_f1[NG];
    __shared__ float4 s_part[NSEG][64];
    __shared__ int    s_wcnt[32];   // (chunk,warp) counts
    __shared__ int    s_woff[32];   // exclusive prefix
    __shared__ int    s_count;
    int lid  = threadIdx.x;
    int pixl = lid & 63;
    int seg  = lid >> 6;
    float x0 = (float)(blockIdx.x*TS), x1 = x0 + (float)(TS-1);
    float y0 = (float)(blockIdx.y*TS), y1 = y0 + (float)(TS-1);
    int warp = lid >> 5, lane = lid & 31;

    // ---- Phase 1: cull + compact (depth order preserved), 2 barriers ----
    float4 f0c[4];
    unsigned m[4];
    bool pass[4];
    #pragma unroll
    for (int c = 0; c < 4; c++) {
        float4 f0 = g_s0[c*256 + lid];
        f0c[c] = f0;
        pass[c] = (f0.w > 0.0f)
               && (f0.x + f0.z >= x0) && (f0.x - f0.z <= x1)
               && (f0.y + f0.z >= y0) && (f0.y - f0.z <= y1);
        m[c] = __ballot_sync(0xffffffffu, pass[c]);
        if (lane == 0) s_wcnt[c*8 + warp] = __popc(m[c]);
    }
    __syncthreads();
    if (warp == 0) {                 // warp-scan of 32 counts
        int v = s_wcnt[lane];
        int s = v;
        #pragma unroll
        for (int d = 1; d < 32; d <<= 1) {
            int n = __shfl_up_sync(0xffffffffu, s, d);
            if (lane >= d) s += n;
        }
        s_woff[lane] = s - v;        // exclusive
        if (lane == 31) s_count = s;
    }
    __syncthreads();
    unsigned lmask = (1u << lane) - 1u;
    #pragma unroll
    for (int c = 0; c < 4; c++) {
        if (pass[c]) {
            int slot = s_woff[c*8 + warp] + __popc(m[c] & lmask);
            s_f0[slot] = f0c[c];
            s_f1[slot] = g_s1[c*256 + lid];
        }
    }
    __syncthreads();
    int count = s_count;

    // ---- Phase 2: segmented front-to-back blend (sequential LDS broadcast) ----
    int L   = (count + NSEG - 1) / NSEG;
    int beg = seg * L;
    int end = min(beg + L, count);
    float fpx = x0 + (float)(pixl & 7), fpy = y0 + (float)(pixl >> 3);
    float T = 1.0f, Cr = 0.0f, Cg = 0.0f, Cb = 0.0f;
    for (int i = beg; i < end; i++) {
        if ((i & 15) == 0 && !__ballot_sync(0xffffffffu, T > 6.1e-5f)) break;
        float4 f0 = s_f0[i];
        float ddx = f0.x - fpx, ddy = f0.y - fpy;
        if (fabsf(ddx) <= f0.z && fabsf(ddy) <= f0.z) {
            float4 f1 = s_f1[i];
            float power = -0.5f*(f1.x*ddx*ddx + f1.z*ddy*ddy) - f1.y*ddx*ddy;
            if (power <= 0.0f) {
                float alpha = fminf(0.99f, f0.w * __expf(power));
                if (alpha >= (1.0f/255.0f)) {
                    float4 f2 = g_s2[(int)f1.w];   // uniform -> L1 broadcast
                    float w = alpha * T;
                    Cr += w*f2.x; Cg += w*f2.y; Cb += w*f2.z;
                    T *= (1.0f - alpha);
                }
            }
        }
    }
    s_part[seg][pixl] = make_float4(Cr, Cg, Cb, T);
    __syncthreads();

    if (lid < 64) {
        float4 p0 = s_part[0][lid];
        float4 p1 = s_part[1][lid];
        float4 p2 = s_part[2][lid];
        float4 p3 = s_part[3][lid];
        float t01 = p0.w * p1.w;
        float cr = p0.x + p0.w*p1.x;
        float cg = p0.y + p0.w*p1.y;
        float cb = p0.z + p0.w*p1.z;
        cr += t01*p2.x; cg += t01*p2.y; cb += t01*p2.z;
        float t012 = t01 * p2.w;
        cr += t012*p3.x; cg += t012*p3.y; cb += t012*p3.z;
        float tt = t012 * p3.w;
        int px = blockIdx.x*TS + (lid & 7);
        int py = blockIdx.y*TS + (lid >> 3);
        int pix = py*IMGW + px;
        out[pix]          = cr + tt*bg[0];
        out[NPIX + pix]   = cg + tt*bg[1];
        out[2*NPIX + pix] = cb + tt*bg[2];
    }
}

extern "C" void kernel_launch(void* const* d_in, const int* in_sizes, int n_in,
                              void* d_out, int out_size)
{
    const float* means3D    = (const float*)d_in[0];
    const float* scales     = (const float*)d_in[1];
    const float* rotations  = (const float*)d_in[2];
    const float* opacities  = (const float*)d_in[3];
    const float* shs        = (const float*)d_in[4];
    const float* viewmatrix = (const float*)d_in[5];
    const float* projmatrix = (const float*)d_in[6];
    const float* campos     = (const float*)d_in[7];
    const float* bg_color   = (const float*)d_in[8];
    float* out = (float*)d_out;

    fused_pre_sort_kernel<<<1, NG>>>(means3D, scales, rotations, opacities, shs,
                                     viewmatrix, projmatrix, campos, out);
    render_kernel<<<dim3(IMGW/TS, IMGH/TS), dim3(256)>>>(bg_color, out);
}

// round 8
// speedup vs baseline: 1.9559x; 1.9559x over previous
#include <cuda_runtime.h>

#define NG   1024
#define IMGW 192
#define IMGH 192
#define NPIX (IMGW*IMGH)
#define TS   8          // tile size
#define NSEG 4          // depth segments per pixel

// Unsorted per-gaussian records:
//  p0 = {gx, gy, radius, opacity_eff (0 if invisible)}
//  p1 = {conA, conB, conC, depth}
//  p2 = {colR, colG, colB, 0}
__device__ float4 g_p0[NG], g_p1[NG], g_p2[NG];

// 32 blocks x 64 threads. Blocks 0-15: geometry for gaussian (bid*64+tid).
// Blocks 16-31: SH color for gaussian ((bid-16)*64+tid).
// The two halves are data-independent -> each thread's serial chain is halved.
__global__ void __launch_bounds__(64) preprocess_kernel(
                                  const float* __restrict__ means,
                                  const float* __restrict__ scales,
                                  const float* __restrict__ rots,
                                  const float* __restrict__ opac,
                                  const float* __restrict__ shs,
                                  const float* __restrict__ view,
                                  const float* __restrict__ proj,
                                  const float* __restrict__ campos,
                                  float* __restrict__ out)
{
    int bid = blockIdx.x;
    if (bid >= 16) {
        // ---------------- color half ----------------
        int i = (bid - 16) * 64 + threadIdx.x;
        float mx = means[3*i], my = means[3*i+1], mz = means[3*i+2];
        float4 t[12];
        const float4* sh4 = reinterpret_cast<const float4*>(shs + i*48);
        #pragma unroll
        for (int w = 0; w < 12; w++) t[w] = __ldg(sh4 + w);

        float dxc = mx - campos[0], dyc = my - campos[1], dzc = mz - campos[2];
        float inv = rsqrtf(dxc*dxc + dyc*dyc + dzc*dzc);
        float x = dxc*inv, y = dyc*inv, z = dzc*inv;
        float xx = x*x, yy = y*y, zz = z*z, xy = x*y, yz = y*z, xz = x*z;
        float bas[16];
        bas[0]  = 0.28209479177387814f;
        bas[1]  = -0.4886025119029199f * y;
        bas[2]  =  0.4886025119029199f * z;
        bas[3]  = -0.4886025119029199f * x;
        bas[4]  =  1.0925484305920792f * xy;
        bas[5]  = -1.0925484305920792f * yz;
        bas[6]  =  0.31539156525252005f * (2.0f*zz - xx - yy);
        bas[7]  = -1.0925484305920792f * xz;
        bas[8]  =  0.5462742152960396f * (xx - yy);
        bas[9]  = -0.5900435899266435f * y * (3.0f*xx - yy);
        bas[10] =  2.890611442640554f  * xy * z;
        bas[11] = -0.4570457994644658f * y * (4.0f*zz - xx - yy);
        bas[12] =  0.3731763325901154f * z * (2.0f*zz - 3.0f*xx - 3.0f*yy);
        bas[13] = -0.4570457994644658f * x * (4.0f*zz - xx - yy);
        bas[14] =  1.445305721320277f  * z * (xx - yy);
        bas[15] = -0.5900435899266435f * x * (xx - yy - 3.0f*zz);

        float col[3] = {0.5f, 0.5f, 0.5f};
        #pragma unroll
        for (int w = 0; w < 12; w++) {
            float v[4] = {t[w].x, t[w].y, t[w].z, t[w].w};
            #pragma unroll
            for (int j = 0; j < 4; j++) {
                const int flat = 4*w + j;
                col[flat % 3] += bas[flat / 3] * v[j];
            }
        }
        g_p2[i] = make_float4(fmaxf(col[0], 0.0f), fmaxf(col[1], 0.0f),
                              fmaxf(col[2], 0.0f), 0.0f);
        return;
    }

    // ---------------- geometry half ----------------
    int i = bid * 64 + threadIdx.x;
    float mx = means[3*i], my = means[3*i+1], mz = means[3*i+2];

    float4 q = __ldg(reinterpret_cast<const float4*>(rots) + i);
    float qr = q.x, qx = q.y, qy = q.z, qz = q.w;
    float sx = scales[3*i], sy = scales[3*i+1], sz = scales[3*i+2];
    float R00 = 1.0f-2.0f*(qy*qy+qz*qz), R01 = 2.0f*(qx*qy-qr*qz), R02 = 2.0f*(qx*qz+qr*qy);
    float R10 = 2.0f*(qx*qy+qr*qz), R11 = 1.0f-2.0f*(qx*qx+qz*qz), R12 = 2.0f*(qy*qz-qr*qx);
    float R20 = 2.0f*(qx*qz-qr*qy), R21 = 2.0f*(qy*qz+qr*qx), R22 = 1.0f-2.0f*(qx*qx+qy*qy);
    float M00=R00*sx, M01=R01*sy, M02=R02*sz;
    float M10=R10*sx, M11=R11*sy, M12=R12*sz;
    float M20=R20*sx, M21=R21*sy, M22=R22*sz;
    float c00 = M00*M00+M01*M01+M02*M02;
    float c01 = M00*M10+M01*M11+M02*M12;
    float c02 = M00*M20+M01*M21+M02*M22;
    float c11 = M10*M10+M11*M11+M12*M12;
    float c12 = M10*M20+M11*M21+M12*M22;
    float c22 = M20*M20+M21*M21+M22*M22;

    float pvx = view[0]*mx + view[1]*my + view[2]*mz + view[3];
    float pvy = view[4]*mx + view[5]*my + view[6]*mz + view[7];
    float pvz = view[8]*mx + view[9]*my + view[10]*mz + view[11];
    float phx = proj[0]*mx + proj[1]*my + proj[2]*mz + proj[3];
    float phy = proj[4]*mx + proj[5]*my + proj[6]*mz + proj[7];
    float phw = proj[12]*mx + proj[13]*my + proj[14]*mz + proj[15];
    float invw = 1.0f / (phw + 1e-7f);
    float gx = ((phx*invw + 1.0f) * (float)IMGW - 1.0f) * 0.5f;
    float gy = ((phy*invw + 1.0f) * (float)IMGH - 1.0f) * 0.5f;
    float depth = pvz;
    bool in_front = depth > 0.2f;
    float tz = in_front ? depth : 1.0f;
    const float lim = 1.3f * 0.5f;
    float txv = fminf(fmaxf(pvx/tz, -lim), lim) * tz;
    float tyv = fminf(fmaxf(pvy/tz, -lim), lim) * tz;
    const float fx = (float)IMGW / (2.0f*0.5f);
    const float fy = (float)IMGH / (2.0f*0.5f);
    float J00 = fx/tz, J02 = -fx*txv/(tz*tz);
    float J11 = fy/tz, J12 = -fy*tyv/(tz*tz);
    float T00 = J00*view[0] + J02*view[8];
    float T01 = J00*view[1] + J02*view[9];
    float T02 = J00*view[2] + J02*view[10];
    float T10 = J11*view[4] + J12*view[8];
    float T11 = J11*view[5] + J12*view[9];
    float T12 = J11*view[6] + J12*view[10];
    float u0 = c00*T00 + c01*T01 + c02*T02;
    float u1 = c01*T00 + c11*T01 + c12*T02;
    float u2 = c02*T00 + c12*T01 + c22*T02;
    float v0 = c00*T10 + c01*T11 + c02*T12;
    float v1 = c01*T10 + c11*T11 + c12*T12;
    float v2 = c02*T10 + c12*T11 + c22*T12;
    float a  = T00*u0 + T01*u1 + T02*u2 + 0.3f;
    float b  = T10*u0 + T11*u1 + T12*u2;
    float cc = T10*v0 + T11*v1 + T12*v2 + 0.3f;
    float det = a*cc - b*b;
    bool pos_det = det > 0.0f;
    float inv_det = pos_det ? 1.0f/det : 0.0f;
    float conA = cc*inv_det, conB = -b*inv_det, conC = a*inv_det;
    float mid = 0.5f*(a + cc);
    float lam = mid + sqrtf(fmaxf(mid*mid - det, 0.1f));
    bool visible = in_front && pos_det;
    float radius = visible ? ceilf(3.0f * sqrtf(lam)) : 0.0f;
    float op = opac[i];

    g_p0[i] = make_float4(gx, gy, radius, visible ? op : 0.0f);
    g_p1[i] = make_float4(conA, conB, conC, depth);

    out[3*NPIX + i]            = radius;
    out[3*NPIX + NG + i]       = (radius > 0.0f) ? 1.0f : 0.0f;
    out[3*NPIX + 2*NG + 2*i]   = gx;
    out[3*NPIX + 2*NG + 2*i+1] = gy;
}

// One block per 8x8 tile, 256 threads = 64 pixels x 4 depth segments.
// Phase 1: order-preserving compaction of overlapping gaussians into shared.
// Phase 2: rank-by-counting depth sort of the tile list (keys unique:
//          depth_bits<<10 | slot; slot order == gid order => stable tie-break).
// Phase 3: segmented front-to-back blend; 4 partials composed associatively.
__global__ void __launch_bounds__(256) render_kernel(const float* __restrict__ bg,
                                                     float* __restrict__ out)
{
    __shared__ float4 s_f0[NG];
    __shared__ float4 s_f1[NG];
    __shared__ unsigned long long s_key[NG];
    __shared__ short  s_ord[NG];
    __shared__ float4 s_part[NSEG][64];
    __shared__ int    s_wcnt[32];
    __shared__ int    s_woff[32];
    __shared__ int    s_count;
    int lid  = threadIdx.x;
    int pixl = lid & 63;
    int seg  = lid >> 6;
    float x0 = (float)(blockIdx.x*TS), x1 = x0 + (float)(TS-1);
    float y0 = (float)(blockIdx.y*TS), y1 = y0 + (float)(TS-1);
    int warp = lid >> 5, lane = lid & 31;

    // ---- Phase 1: cull + compact (slot order == gid order) ----
    float4 f0c[4];
    unsigned m[4];
    bool pass[4];
    #pragma unroll
    for (int c = 0; c < 4; c++) {
        float4 f0 = g_p0[c*256 + lid];
        f0c[c] = f0;
        pass[c] = (f0.w > 0.0f)
               && (f0.x + f0.z >= x0) && (f0.x - f0.z <= x1)
               && (f0.y + f0.z >= y0) && (f0.y - f0.z <= y1);
        m[c] = __ballot_sync(0xffffffffu, pass[c]);
        if (lane == 0) s_wcnt[c*8 + warp] = __popc(m[c]);
    }
    __syncthreads();
    if (warp == 0) {
        int v = s_wcnt[lane];
        int s = v;
        #pragma unroll
        for (int d = 1; d < 32; d <<= 1) {
            int n = __shfl_up_sync(0xffffffffu, s, d);
            if (lane >= d) s += n;
        }
        s_woff[lane] = s - v;
        if (lane == 31) s_count = s;
    }
    __syncthreads();
    unsigned lmask = (1u << lane) - 1u;
    #pragma unroll
    for (int c = 0; c < 4; c++) {
        if (pass[c]) {
            int gid  = c*256 + lid;
            int slot = s_woff[c*8 + warp] + __popc(m[c] & lmask);
            float4 f1 = g_p1[gid];
            s_f0[slot] = f0c[c];
            s_key[slot] = ((unsigned long long)__float_as_uint(f1.w) << 10)
                        | (unsigned long long)slot;
            s_f1[slot] = make_float4(f1.x, f1.y, f1.z, (float)gid);
        }
    }
    __syncthreads();
    int count = s_count;

    // ---- Phase 2: rank-by-counting sort (keys unique) ----
    for (int s = lid; s < count; s += 256) {
        unsigned long long k = s_key[s];
        int r = 0;
        for (int j = 0; j < count; j++)      // s_key[j] is a block-wide broadcast
            r += (s_key[j] < k) ? 1 : 0;
        s_ord[r] = (short)s;
    }
    __syncthreads();

    // ---- Phase 3: segmented front-to-back blend ----
    int L   = (count + NSEG - 1) / NSEG;
    int beg = seg * L;
    int end = min(beg + L, count);
    float fpx = x0 + (float)(pixl & 7), fpy = y0 + (float)(pixl >> 3);
    float T = 1.0f, Cr = 0.0f, Cg = 0.0f, Cb = 0.0f;
    for (int i = beg; i < end; i++) {
        if ((i & 15) == 0 && !__ballot_sync(0xffffffffu, T > 6.1e-5f)) break;
        int slot = s_ord[i];                 // LDS broadcast
        float4 f0 = s_f0[slot];
        float ddx = f0.x - fpx, ddy = f0.y - fpy;
        if (fabsf(ddx) <= f0.z && fabsf(ddy) <= f0.z) {
            float4 f1 = s_f1[slot];
            float power = -0.5f*(f1.x*ddx*ddx + f1.z*ddy*ddy) - f1.y*ddx*ddy;
            if (power <= 0.0f) {
                float alpha = fminf(0.99f, f0.w * __expf(power));
                if (alpha >= (1.0f/255.0f)) {
                    float4 f2 = g_p2[(int)f1.w];   // uniform -> L1 broadcast
                    float w = alpha * T;
                    Cr += w*f2.x; Cg += w*f2.y; Cb += w*f2.z;
                    T *= (1.0f - alpha);
                }
            }
        }
    }
    s_part[seg][pixl] = make_float4(Cr, Cg, Cb, T);
    __syncthreads();

    if (lid < 64) {
        float4 p0 = s_part[0][lid];
        float4 p1 = s_part[1][lid];
        float4 p2 = s_part[2][lid];
        float4 p3 = s_part[3][lid];
        float t01 = p0.w * p1.w;
        float cr = p0.x + p0.w*p1.x;
        float cg = p0.y + p0.w*p1.y;
        float cb = p0.z + p0.w*p1.z;
        cr += t01*p2.x; cg += t01*p2.y; cb += t01*p2.z;
        float t012 = t01 * p2.w;
        cr += t012*p3.x; cg += t012*p3.y; cb += t012*p3.z;
        float tt = t012 * p3.w;
        int px = blockIdx.x*TS + (lid & 7);
        int py = blockIdx.y*TS + (lid >> 3);
        int pix = py*IMGW + px;
        out[pix]          = cr + tt*bg[0];
        out[NPIX + pix]   = cg + tt*bg[1];
        out[2*NPIX + pix] = cb + tt*bg[2];
    }
}

extern "C" void kernel_launch(void* const* d_in, const int* in_sizes, int n_in,
                              void* d_out, int out_size)
{
    const float* means3D    = (const float*)d_in[0];
    const float* scales     = (const float*)d_in[1];
    const float* rotations  = (const float*)d_in[2];
    const float* opacities  = (const float*)d_in[3];
    const float* shs        = (const float*)d_in[4];
    const float* viewmatrix = (const float*)d_in[5];
    const float* projmatrix = (const float*)d_in[6];
    const float* campos     = (const float*)d_in[7];
    const float* bg_color   = (const float*)d_in[8];
    float* out = (float*)d_out;

    preprocess_kernel<<<32, 64>>>(means3D, scales, rotations, opacities, shs,
                                  viewmatrix, projmatrix, campos, out);
    render_kernel<<<dim3(IMGW/TS, IMGH/TS), dim3(256)>>>(bg_color, out);
}

// round 9
// speedup vs baseline: 2.3821x; 1.2179x over previous
#include <cuda_runtime.h>

#define NG   1024
#define IMGW 192
#define IMGH 192
#define NPIX (IMGW*IMGH)
#define TS   8          // tile size
#define NSEG 8          // depth segments per pixel
#define NTHR 512        // 64 pixels x 8 segments

// Unsorted per-gaussian records:
//  p0 = {gx, gy, radius, opacity_eff (0 if invisible)}
//  p1 = {conA, conB, conC, depth}
//  p2 = {colR, colG, colB, 0}
__device__ float4 g_p0[NG], g_p1[NG], g_p2[NG];

// 32 blocks x 64 threads. Blocks 0-15: geometry. Blocks 16-31: SH color.
__global__ void __launch_bounds__(64) preprocess_kernel(
                                  const float* __restrict__ means,
                                  const float* __restrict__ scales,
                                  const float* __restrict__ rots,
                                  const float* __restrict__ opac,
                                  const float* __restrict__ shs,
                                  const float* __restrict__ view,
                                  const float* __restrict__ proj,
                                  const float* __restrict__ campos,
                                  float* __restrict__ out)
{
    int bid = blockIdx.x;
    if (bid >= 16) {
        // ---------------- color half ----------------
        int i = (bid - 16) * 64 + threadIdx.x;
        float mx = means[3*i], my = means[3*i+1], mz = means[3*i+2];
        float4 t[12];
        const float4* sh4 = reinterpret_cast<const float4*>(shs + i*48);
        #pragma unroll
        for (int w = 0; w < 12; w++) t[w] = __ldg(sh4 + w);

        float dxc = mx - campos[0], dyc = my - campos[1], dzc = mz - campos[2];
        float inv = rsqrtf(dxc*dxc + dyc*dyc + dzc*dzc);
        float x = dxc*inv, y = dyc*inv, z = dzc*inv;
        float xx = x*x, yy = y*y, zz = z*z, xy = x*y, yz = y*z, xz = x*z;
        float bas[16];
        bas[0]  = 0.28209479177387814f;
        bas[1]  = -0.4886025119029199f * y;
        bas[2]  =  0.4886025119029199f * z;
        bas[3]  = -0.4886025119029199f * x;
        bas[4]  =  1.0925484305920792f * xy;
        bas[5]  = -1.0925484305920792f * yz;
        bas[6]  =  0.31539156525252005f * (2.0f*zz - xx - yy);
        bas[7]  = -1.0925484305920792f * xz;
        bas[8]  =  0.5462742152960396f * (xx - yy);
        bas[9]  = -0.5900435899266435f * y * (3.0f*xx - yy);
        bas[10] =  2.890611442640554f  * xy * z;
        bas[11] = -0.4570457994644658f * y * (4.0f*zz - xx - yy);
        bas[12] =  0.3731763325901154f * z * (2.0f*zz - 3.0f*xx - 3.0f*yy);
        bas[13] = -0.4570457994644658f * x * (4.0f*zz - xx - yy);
        bas[14] =  1.445305721320277f  * z * (xx - yy);
        bas[15] = -0.5900435899266435f * x * (xx - yy - 3.0f*zz);

        float col[3] = {0.5f, 0.5f, 0.5f};
        #pragma unroll
        for (int w = 0; w < 12; w++) {
            float v[4] = {t[w].x, t[w].y, t[w].z, t[w].w};
            #pragma unroll
            for (int j = 0; j < 4; j++) {
                const int flat = 4*w + j;
                col[flat % 3] += bas[flat / 3] * v[j];
            }
        }
        g_p2[i] = make_float4(fmaxf(col[0], 0.0f), fmaxf(col[1], 0.0f),
                              fmaxf(col[2], 0.0f), 0.0f);
        return;
    }

    // ---------------- geometry half ----------------
    int i = bid * 64 + threadIdx.x;
    float mx = means[3*i], my = means[3*i+1], mz = means[3*i+2];

    float4 q = __ldg(reinterpret_cast<const float4*>(rots) + i);
    float qr = q.x, qx = q.y, qy = q.z, qz = q.w;
    float sx = scales[3*i], sy = scales[3*i+1], sz = scales[3*i+2];
    float R00 = 1.0f-2.0f*(qy*qy+qz*qz), R01 = 2.0f*(qx*qy-qr*qz), R02 = 2.0f*(qx*qz+qr*qy);
    float R10 = 2.0f*(qx*qy+qr*qz), R11 = 1.0f-2.0f*(qx*qx+qz*qz), R12 = 2.0f*(qy*qz-qr*qx);
    float R20 = 2.0f*(qx*qz-qr*qy), R21 = 2.0f*(qy*qz+qr*qx), R22 = 1.0f-2.0f*(qx*qx+qy*qy);
    float M00=R00*sx, M01=R01*sy, M02=R02*sz;
    float M10=R10*sx, M11=R11*sy, M12=R12*sz;
    float M20=R20*sx, M21=R21*sy, M22=R22*sz;
    float c00 = M00*M00+M01*M01+M02*M02;
    float c01 = M00*M10+M01*M11+M02*M12;
    float c02 = M00*M20+M01*M21+M02*M22;
    float c11 = M10*M10+M11*M11+M12*M12;
    float c12 = M10*M20+M11*M21+M12*M22;
    float c22 = M20*M20+M21*M21+M22*M22;

    float pvx = view[0]*mx + view[1]*my + view[2]*mz + view[3];
    float pvy = view[4]*mx + view[5]*my + view[6]*mz + view[7];
    float pvz = view[8]*mx + view[9]*my + view[10]*mz + view[11];
    float phx = proj[0]*mx + proj[1]*my + proj[2]*mz + proj[3];
    float phy = proj[4]*mx + proj[5]*my + proj[6]*mz + proj[7];
    float phw = proj[12]*mx + proj[13]*my + proj[14]*mz + proj[15];
    float invw = 1.0f / (phw + 1e-7f);
    float gx = ((phx*invw + 1.0f) * (float)IMGW - 1.0f) * 0.5f;
    float gy = ((phy*invw + 1.0f) * (float)IMGH - 1.0f) * 0.5f;
    float depth = pvz;
    bool in_front = depth > 0.2f;
    float tz = in_front ? depth : 1.0f;
    const float lim = 1.3f * 0.5f;
    float txv = fminf(fmaxf(pvx/tz, -lim), lim) * tz;
    float tyv = fminf(fmaxf(pvy/tz, -lim), lim) * tz;
    const float fx = (float)IMGW / (2.0f*0.5f);
    const float fy = (float)IMGH / (2.0f*0.5f);
    float J00 = fx/tz, J02 = -fx*txv/(tz*tz);
    float J11 = fy/tz, J12 = -fy*tyv/(tz*tz);
    float T00 = J00*view[0] + J02*view[8];
    float T01 = J00*view[1] + J02*view[9];
    float T02 = J00*view[2] + J02*view[10];
    float T10 = J11*view[4] + J12*view[8];
    float T11 = J11*view[5] + J12*view[9];
    float T12 = J11*view[6] + J12*view[10];
    float u0 = c00*T00 + c01*T01 + c02*T02;
    float u1 = c01*T00 + c11*T01 + c12*T02;
    float u2 = c02*T00 + c12*T01 + c22*T02;
    float v0 = c00*T10 + c01*T11 + c02*T12;
    float v1 = c01*T10 + c11*T11 + c12*T12;
    float v2 = c02*T10 + c12*T11 + c22*T12;
    float a  = T00*u0 + T01*u1 + T02*u2 + 0.3f;
    float b  = T10*u0 + T11*u1 + T12*u2;
    float cc = T10*v0 + T11*v1 + T12*v2 + 0.3f;
    float det = a*cc - b*b;
    bool pos_det = det > 0.0f;
    float inv_det = pos_det ? 1.0f/det : 0.0f;
    float conA = cc*inv_det, conB = -b*inv_det, conC = a*inv_det;
    float mid = 0.5f*(a + cc);
    float lam = mid + sqrtf(fmaxf(mid*mid - det, 0.1f));
    bool visible = in_front && pos_det;
    float radius = visible ? ceilf(3.0f * sqrtf(lam)) : 0.0f;
    float op = opac[i];

    g_p0[i] = make_float4(gx, gy, radius, visible ? op : 0.0f);
    g_p1[i] = make_float4(conA, conB, conC, depth);

    out[3*NPIX + i]            = radius;
    out[3*NPIX + NG + i]       = (radius > 0.0f) ? 1.0f : 0.0f;
    out[3*NPIX + 2*NG + 2*i]   = gx;
    out[3*NPIX + 2*NG + 2*i+1] = gy;
}

// One block per 8x8 tile, 512 threads = 64 pixels x 8 depth segments.
// Phase 1: order-preserving compaction of overlapping gaussians (f0 -> shared).
// Phase 2: rank-by-counting depth sort. Key = depth_bits<<20 | gid<<10 | slot
//          (unique; gid tie-break == stable global argsort).
// Phase 3: segmented front-to-back blend; conic/color read via uniform L1
//          broadcast only on bbox-pass iterations; 8 partials composed.
__global__ void __launch_bounds__(NTHR) render_kernel(const float* __restrict__ bg,
                                                      float* __restrict__ out)
{
    __shared__ float4 s_f0[NG];
    __shared__ unsigned long long s_key[NG];
    __shared__ unsigned long long s_srt[NG];
    __shared__ float4 s_part[NSEG][64];
    __shared__ int    s_wcnt[32];
    __shared__ int    s_woff[32];
    __shared__ int    s_count;
    int lid  = threadIdx.x;
    int pixl = lid & 63;
    int seg  = lid >> 6;
    float x0 = (float)(blockIdx.x*TS), x1 = x0 + (float)(TS-1);
    float y0 = (float)(blockIdx.y*TS), y1 = y0 + (float)(TS-1);
    int warp = lid >> 5, lane = lid & 31;

    // ---- Phase 1: cull + compact (slot order == gid order), 2 chunks of 512 ----
    float4 f0c[2];
    unsigned m[2];
    bool pass[2];
    #pragma unroll
    for (int c = 0; c < 2; c++) {
        float4 f0 = g_p0[c*NTHR + lid];
        f0c[c] = f0;
        pass[c] = (f0.w > 0.0f)
               && (f0.x + f0.z >= x0) && (f0.x - f0.z <= x1)
               && (f0.y + f0.z >= y0) && (f0.y - f0.z <= y1);
        m[c] = __ballot_sync(0xffffffffu, pass[c]);
        if (lane == 0) s_wcnt[c*16 + warp] = __popc(m[c]);
    }
    __syncthreads();
    if (warp == 0) {
        int v = s_wcnt[lane];
        int s = v;
        #pragma unroll
        for (int d = 1; d < 32; d <<= 1) {
            int n = __shfl_up_sync(0xffffffffu, s, d);
            if (lane >= d) s += n;
        }
        s_woff[lane] = s - v;
        if (lane == 31) s_count = s;
    }
    __syncthreads();
    unsigned lmask = (1u << lane) - 1u;
    #pragma unroll
    for (int c = 0; c < 2; c++) {
        if (pass[c]) {
            int gid  = c*NTHR + lid;
            int slot = s_woff[c*16 + warp] + __popc(m[c] & lmask);
            s_f0[slot] = f0c[c];
            float d = g_p1[gid].w;
            s_key[slot] = ((unsigned long long)__float_as_uint(d) << 20)
                        | ((unsigned long long)gid << 10)
                        | (unsigned long long)slot;
        }
    }
    __syncthreads();
    int count = s_count;

    // ---- Phase 2: rank-by-counting sort (keys unique) ----
    for (int s = lid; s < count; s += NTHR) {
        unsigned long long k = s_key[s];
        int r = 0;
        for (int j = 0; j < count; j++)      // block-wide LDS broadcast
            r += (s_key[j] < k) ? 1 : 0;
        s_srt[r] = k;
    }
    __syncthreads();

    // ---- Phase 3: segmented front-to-back blend ----
    int L   = (count + NSEG - 1) / NSEG;
    int beg = seg * L;
    int end = min(beg + L, count);
    float fpx = x0 + (float)(pixl & 7), fpy = y0 + (float)(pixl >> 3);
    float T = 1.0f, Cr = 0.0f, Cg = 0.0f, Cb = 0.0f;
    for (int i = beg; i < end; i++) {
        if ((i & 15) == 0 && !__ballot_sync(0xffffffffu, T > 6.1e-5f)) break;
        unsigned long long key = s_srt[i];
        float4 f0 = s_f0[(int)(key & 1023ULL)];
        float ddx = f0.x - fpx, ddy = f0.y - fpy;
        if (fabsf(ddx) <= f0.z && fabsf(ddy) <= f0.z) {
            int gid = (int)((key >> 10) & 1023ULL);
            float4 f1 = __ldg(&g_p1[gid]);   // uniform -> L1 broadcast
            float power = -0.5f*(f1.x*ddx*ddx + f1.z*ddy*ddy) - f1.y*ddx*ddy;
            if (power <= 0.0f) {
                float alpha = fminf(0.99f, f0.w * __expf(power));
                if (alpha >= (1.0f/255.0f)) {
                    float4 f2 = __ldg(&g_p2[gid]);
                    float w = alpha * T;
                    Cr += w*f2.x; Cg += w*f2.y; Cb += w*f2.z;
                    T *= (1.0f - alpha);
                }
            }
        }
    }
    s_part[seg][pixl] = make_float4(Cr, Cg, Cb, T);
    __syncthreads();

    if (lid < 64) {
        float cr = 0.0f, cg = 0.0f, cb = 0.0f, tt = 1.0f;
        #pragma unroll
        for (int s = 0; s < NSEG; s++) {
            float4 p = s_part[s][lid];
            cr += tt*p.x; cg += tt*p.y; cb += tt*p.z;
            tt *= p.w;
        }
        int px = blockIdx.x*TS + (lid & 7);
        int py = blockIdx.y*TS + (lid >> 3);
        int pix = py*IMGW + px;
        out[pix]          = cr + tt*bg[0];
        out[NPIX + pix]   = cg + tt*bg[1];
        out[2*NPIX + pix] = cb + tt*bg[2];
    }
}

extern "C" void kernel_launch(void* const* d_in, const int* in_sizes, int n_in,
                              void* d_out, int out_size)
{
    const float* means3D    = (const float*)d_in[0];
    const float* scales     = (const float*)d_in[1];
    const float* rotations  = (const float*)d_in[2];
    const float* opacities  = (const float*)d_in[3];
    const float* shs        = (const float*)d_in[4];
    const float* viewmatrix = (const float*)d_in[5];
    const float* projmatrix = (const float*)d_in[6];
    const float* campos     = (const float*)d_in[7];
    const float* bg_color   = (const float*)d_in[8];
    float* out = (float*)d_out;

    preprocess_kernel<<<32, 64>>>(means3D, scales, rotations, opacities, shs,
                                  viewmatrix, projmatrix, campos, out);
    render_kernel<<<dim3(IMGW/TS, IMGH/TS), dim3(NTHR)>>>(bg_color, out);
}